// round 3
// baseline (speedup 1.0000x reference)
#include <cuda_runtime.h>
#include <cstdint>

#define T_TOK 2048
#define HID   2048
#define NEXP  64
#define IDIM  768
#define TOPK  8
#define NPAIR (T_TOK*TOPK)   // 16384

#define PITCH 40
#define STG   (256*PITCH)           // floats per stage (A 128 rows + B 128 rows)
#define SMEM_BYTES (2*STG*4)        // 81920 B

// ---------------- device scratch (static, allocation-free) ----------------
__device__ int   g_topk_idx[NPAIR];
__device__ float g_topk_w[NPAIR];
__device__ int   g_counts[NEXP];
__device__ int   g_offsets[NEXP];
__device__ int   g_list[NEXP*T_TOK];
__device__ float g_hbuf[(size_t)(NPAIR+128)*IDIM];
__device__ float g_outbuf[(size_t)NPAIR*HID];

// ---------------- helpers ----------------
__device__ __forceinline__ float cvt_tf32(float x) {
    uint32_t u; asm("cvt.rna.tf32.f32 %0, %1;" : "=r"(u) : "f"(x));
    return __uint_as_float(u);
}

__device__ __forceinline__ void mma_tf32(float* c, const uint32_t* a, uint32_t b0, uint32_t b1) {
    asm volatile(
        "mma.sync.aligned.m16n8k8.row.col.f32.tf32.tf32.f32 "
        "{%0,%1,%2,%3}, {%4,%5,%6,%7}, {%8,%9}, {%0,%1,%2,%3};\n"
        : "+f"(c[0]), "+f"(c[1]), "+f"(c[2]), "+f"(c[3])
        : "r"(a[0]), "r"(a[1]), "r"(a[2]), "r"(a[3]), "r"(b0), "r"(b1));
}

__device__ __forceinline__ void cp_async16(uint32_t smem_addr, const void* gptr, int src_bytes) {
    asm volatile("cp.async.cg.shared.global [%0], [%1], 16, %2;\n"
                 :: "r"(smem_addr), "l"(gptr), "r"(src_bytes));
}
__device__ __forceinline__ void cp_commit() { asm volatile("cp.async.commit_group;\n"); }
template<int N> __device__ __forceinline__ void cp_wait() {
    asm volatile("cp.async.wait_group %0;\n" :: "n"(N));
}

// ---------------- 1. router ----------------
__global__ void router_kernel(const float* __restrict__ x, const float* __restrict__ gw) {
    __shared__ float Xs[16][68];
    __shared__ float Gs[64][68];
    __shared__ float Ls[16][64];
    const int tid = threadIdx.x;
    const int t0  = blockIdx.x * 16;
    const int tl  = tid & 15;
    const int eg  = tid >> 4;

    float acc[4] = {0.f, 0.f, 0.f, 0.f};

    for (int kk = 0; kk < HID; kk += 64) {
        {
            int r = tid >> 4, c = (tid & 15) * 4;
            float4 v = *(const float4*)(x + (size_t)(t0 + r) * HID + kk + c);
            Xs[r][c] = v.x; Xs[r][c+1] = v.y; Xs[r][c+2] = v.z; Xs[r][c+3] = v.w;
        }
        #pragma unroll
        for (int i = 0; i < 4; i++) {
            int idx = i * 256 + tid;
            int r = idx >> 4, c = (idx & 15) * 4;
            float4 v = *(const float4*)(gw + (size_t)r * HID + kk + c);
            Gs[r][c] = v.x; Gs[r][c+1] = v.y; Gs[r][c+2] = v.z; Gs[r][c+3] = v.w;
        }
        __syncthreads();
        #pragma unroll 4
        for (int k = 0; k < 64; k += 4) {
            float4 xv = *(const float4*)&Xs[tl][k];
            #pragma unroll
            for (int j = 0; j < 4; j++) {
                float4 gv = *(const float4*)&Gs[eg*4 + j][k];
                acc[j] += xv.x*gv.x + xv.y*gv.y + xv.z*gv.z + xv.w*gv.w;
            }
        }
        __syncthreads();
    }
    #pragma unroll
    for (int j = 0; j < 4; j++) Ls[tl][eg*4 + j] = acc[j];
    __syncthreads();

    const int wid = tid >> 5, lane = tid & 31;
    for (int j = 0; j < 2; j++) {
        const int tok = wid * 2 + j;
        float v0 = Ls[tok][lane];
        float v1 = Ls[tok][lane + 32];
        bool s0 = false, s1 = false;
        float vals[8]; int idxs[8];
        #pragma unroll
        for (int r = 0; r < 8; r++) {
            float bv = -1e30f; int bi = 1 << 20;
            if (!s0) { bv = v0; bi = lane; }
            if (!s1 && (v1 > bv || (v1 == bv && lane + 32 < bi))) { bv = v1; bi = lane + 32; }
            #pragma unroll
            for (int o = 16; o > 0; o >>= 1) {
                float ov = __shfl_xor_sync(0xffffffffu, bv, o);
                int   oi = __shfl_xor_sync(0xffffffffu, bi, o);
                if (ov > bv || (ov == bv && oi < bi)) { bv = ov; bi = oi; }
            }
            vals[r] = bv; idxs[r] = bi;
            if (bi == lane)      s0 = true;
            if (bi == lane + 32) s1 = true;
        }
        if (lane == 0) {
            float m = vals[0];
            float w[8]; float sum = 0.f;
            #pragma unroll
            for (int r = 0; r < 8; r++) { w[r] = __expf(vals[r] - m); sum += w[r]; }
            float inv = 1.f / sum;
            int gt = t0 + tok;
            #pragma unroll
            for (int r = 0; r < 8; r++) {
                g_topk_idx[gt*TOPK + r] = idxs[r];
                g_topk_w  [gt*TOPK + r] = w[r] * inv;
            }
        }
    }
}

// ---------------- 2. bucketing ----------------
__global__ void bucket_kernel() {
    const int e = blockIdx.x;
    const int tid = threadIdx.x;
    __shared__ int warp_tot[8];
    __shared__ int base_s;
    if (tid == 0) base_s = 0;
    __syncthreads();
    const int wid = tid >> 5, lane = tid & 31;
    for (int t0 = 0; t0 < T_TOK; t0 += 256) {
        int t = t0 + tid;
        int slot = -1;
        #pragma unroll
        for (int k = 0; k < TOPK; k++)
            if (g_topk_idx[t*TOPK + k] == e) slot = k;
        unsigned m = __ballot_sync(0xffffffffu, slot >= 0);
        if (lane == 0) warp_tot[wid] = __popc(m);
        __syncthreads();
        int wbase = base_s;
        for (int i = 0; i < wid; i++) wbase += warp_tot[i];
        if (slot >= 0) {
            int pos = wbase + __popc(m & ((1u << lane) - 1u));
            g_list[e*T_TOK + pos] = t*TOPK + slot;
        }
        __syncthreads();
        if (tid == 0) {
            int tot = 0;
            for (int i = 0; i < 8; i++) tot += warp_tot[i];
            base_s += tot;
        }
        __syncthreads();
    }
    if (tid == 0) g_counts[e] = base_s;
}

__global__ void offsets_kernel() {
    if (threadIdx.x == 0 && blockIdx.x == 0) {
        int s = 0;
        for (int e = 0; e < NEXP; e++) { g_offsets[e] = s; s += g_counts[e]; }
    }
}

// ---------------- shared GEMM pieces ----------------
// stage layout: rows 0..127 = A (128 x 32), rows 128..255 = B (128 x 32), pitch 40.
// k-permutation: mma step s, hardware-k h -> smem col 8s + 2*(h&3) + (h>>2).

__device__ __forceinline__ void convert_stage(float* st, int tid) {
    #pragma unroll
    for (int it = 0; it < 8; it++) {
        int fid = it * 256 + tid;
        int r = fid >> 3, c4 = (fid & 7) * 4;
        float* p = st + r * PITCH + c4;
        float4 v = *(float4*)p;
        v.x = cvt_tf32(v.x); v.y = cvt_tf32(v.y);
        v.z = cvt_tf32(v.z); v.w = cvt_tf32(v.w);
        *(float4*)p = v;
    }
}

// ---------------- 3. GEMM1: h = silu(X Wg^T) * (X Wu^T) --------------------
__global__ void __launch_bounds__(256, 2)
gemm_gateup(const float* __restrict__ hidden,
            const float* __restrict__ wg,
            const float* __restrict__ wu) {
    const int mb = blockIdx.x, nb = blockIdx.y, e = blockIdx.z;
    const int cnt = g_counts[e];
    if (mb * 128 >= cnt) return;
    const int base = g_offsets[e];

    extern __shared__ float smem[];
    __shared__ int toks_s[128];

    const int tid = threadIdx.x;
    if (tid < 128) {
        int m = mb * 128 + tid;
        toks_s[tid] = (m < cnt) ? (g_list[e*T_TOK + m] >> 3) : -1;
    }
    __syncthreads();

    const int n0 = nb * 64;
    const float* wg_p = wg + ((size_t)e * IDIM + n0) * HID;
    const float* wu_p = wu + ((size_t)e * IDIM + n0) * HID;

    const uint32_t smem_u = (uint32_t)__cvta_generic_to_shared(smem);

    auto load_stage = [&](int kt, int s) {
        const int kk = kt * 32;
        const uint32_t st = smem_u + (uint32_t)(s * STG) * 4u;
        #pragma unroll
        for (int it = 0; it < 4; it++) {          // A: 1024 float4
            int fid = it * 256 + tid;
            int r = fid >> 3, c = (fid & 7) * 4;
            int tok = toks_s[r];
            const float* src = (tok >= 0) ? hidden + (size_t)tok * HID + kk + c : hidden;
            cp_async16(st + (uint32_t)(r * PITCH + c) * 4u, src, (tok >= 0) ? 16 : 0);
        }
        #pragma unroll
        for (int it = 0; it < 4; it++) {          // B: 1024 float4 (64 gate + 64 up)
            int fid = it * 256 + tid;
            int r = fid >> 3, c = (fid & 7) * 4;
            const float* src = (r < 64) ? wg_p + (size_t)r * HID + kk + c
                                        : wu_p + (size_t)(r - 64) * HID + kk + c;
            cp_async16(st + (uint32_t)((128 + r) * PITCH + c) * 4u, src, 16);
        }
    };

    float cg[2][4][4], cu[2][4][4];
    #pragma unroll
    for (int a = 0; a < 2; a++)
        #pragma unroll
        for (int b = 0; b < 4; b++)
            #pragma unroll
            for (int c = 0; c < 4; c++) { cg[a][b][c] = 0.f; cu[a][b][c] = 0.f; }

    const int wid = tid >> 5, lane = tid & 31;
    const int wm = wid & 3, wn = wid >> 2;
    const int grp = lane >> 2, tg = lane & 3;

    const int KT = HID / 32;                       // 64
    load_stage(0, 0); cp_commit();

    for (int kt = 0; kt < KT; kt++) {
        cp_wait<0>();
        __syncthreads();
        float* st = smem + (kt & 1) * STG;
        convert_stage(st, tid);
        if (kt + 1 < KT) load_stage(kt + 1, (kt + 1) & 1);
        cp_commit();
        __syncthreads();

        #pragma unroll
        for (int s = 0; s < 4; s++) {
            const int colb = s * 8 + tg * 2;
            uint32_t a[2][4];
            #pragma unroll
            for (int mt = 0; mt < 2; mt++) {
                int r0 = wm * 32 + mt * 16 + grp;
                float2 x = *(const float2*)&st[ r0      * PITCH + colb];
                float2 y = *(const float2*)&st[(r0 + 8) * PITCH + colb];
                a[mt][0] = __float_as_uint(x.x); a[mt][1] = __float_as_uint(y.x);
                a[mt][2] = __float_as_uint(x.y); a[mt][3] = __float_as_uint(y.y);
            }
            #pragma unroll
            for (int nt = 0; nt < 4; nt++) {
                int rn = 128 + wn * 32 + nt * 8 + grp;
                float2 g = *(const float2*)&st[ rn       * PITCH + colb];
                float2 u = *(const float2*)&st[(rn + 64) * PITCH + colb];
                uint32_t g0 = __float_as_uint(g.x), g1 = __float_as_uint(g.y);
                uint32_t u0 = __float_as_uint(u.x), u1 = __float_as_uint(u.y);
                mma_tf32(cg[0][nt], a[0], g0, g1);
                mma_tf32(cg[1][nt], a[1], g0, g1);
                mma_tf32(cu[0][nt], a[0], u0, u1);
                mma_tf32(cu[1][nt], a[1], u0, u1);
            }
        }
    }

    // ---- epilogue: silu(g)*u -> g_hbuf ----
    #pragma unroll
    for (int mt = 0; mt < 2; mt++) {
        #pragma unroll
        for (int half = 0; half < 2; half++) {
            int row = wm * 32 + mt * 16 + half * 8 + grp;
            int m = mb * 128 + row;
            if (m < cnt) {
                float* hrow = g_hbuf + (size_t)(base + m) * IDIM + n0;
                #pragma unroll
                for (int nt = 0; nt < 4; nt++) {
                    int col = wn * 32 + nt * 8 + tg * 2;
                    float g0 = cg[mt][nt][half*2 + 0], u0 = cu[mt][nt][half*2 + 0];
                    float g1 = cg[mt][nt][half*2 + 1], u1 = cu[mt][nt][half*2 + 1];
                    float2 hv;
                    hv.x = g0 * u0 / (1.f + __expf(-g0));
                    hv.y = g1 * u1 / (1.f + __expf(-g1));
                    *(float2*)(hrow + col) = hv;
                }
            }
        }
    }
}

// ---------------- 4. GEMM2: y = (h Wd^T) * combine_w -> g_outbuf ----------
__global__ void __launch_bounds__(256, 2)
gemm_down(const float* __restrict__ wd) {
    const int mb = blockIdx.x, nb = blockIdx.y, e = blockIdx.z;
    const int cnt = g_counts[e];
    if (mb * 128 >= cnt) return;
    const int base = g_offsets[e];

    extern __shared__ float smem[];
    __shared__ int pairs_s[128];

    const int tid = threadIdx.x;
    if (tid < 128) {
        int m = mb * 128 + tid;
        pairs_s[tid] = (m < cnt) ? g_list[e*T_TOK + m] : -1;
    }
    __syncthreads();

    const int n0 = nb * 128;
    const float* wd_p  = wd + ((size_t)e * HID + n0) * IDIM;
    const float* arow0 = g_hbuf + (size_t)(base + mb * 128) * IDIM;

    const uint32_t smem_u = (uint32_t)__cvta_generic_to_shared(smem);

    auto load_stage = [&](int kt, int s) {
        const int kk = kt * 32;
        const uint32_t st = smem_u + (uint32_t)(s * STG) * 4u;
        #pragma unroll
        for (int it = 0; it < 4; it++) {
            int fid = it * 256 + tid;
            int r = fid >> 3, c = (fid & 7) * 4;
            bool val = pairs_s[r] >= 0;
            const float* src = val ? arow0 + (size_t)r * IDIM + kk + c : g_hbuf;
            cp_async16(st + (uint32_t)(r * PITCH + c) * 4u, src, val ? 16 : 0);
        }
        #pragma unroll
        for (int it = 0; it < 4; it++) {
            int fid = it * 256 + tid;
            int r = fid >> 3, c = (fid & 7) * 4;
            cp_async16(st + (uint32_t)((128 + r) * PITCH + c) * 4u,
                       wd_p + (size_t)r * IDIM + kk + c, 16);
        }
    };

    float cd[2][8][4];
    #pragma unroll
    for (int a = 0; a < 2; a++)
        #pragma unroll
        for (int b = 0; b < 8; b++)
            #pragma unroll
            for (int c = 0; c < 4; c++) cd[a][b][c] = 0.f;

    const int wid = tid >> 5, lane = tid & 31;
    const int wm = wid & 3, wn = wid >> 2;
    const int grp = lane >> 2, tg = lane & 3;

    const int KT = IDIM / 32;                      // 24
    load_stage(0, 0); cp_commit();

    for (int kt = 0; kt < KT; kt++) {
        cp_wait<0>();
        __syncthreads();
        float* st = smem + (kt & 1) * STG;
        convert_stage(st, tid);
        if (kt + 1 < KT) load_stage(kt + 1, (kt + 1) & 1);
        cp_commit();
        __syncthreads();

        #pragma unroll
        for (int s = 0; s < 4; s++) {
            const int colb = s * 8 + tg * 2;
            uint32_t a[2][4];
            #pragma unroll
            for (int mt = 0; mt < 2; mt++) {
                int r0 = wm * 32 + mt * 16 + grp;
                float2 x = *(const float2*)&st[ r0      * PITCH + colb];
                float2 y = *(const float2*)&st[(r0 + 8) * PITCH + colb];
                a[mt][0] = __float_as_uint(x.x); a[mt][1] = __float_as_uint(y.x);
                a[mt][2] = __float_as_uint(x.y); a[mt][3] = __float_as_uint(y.y);
            }
            #pragma unroll
            for (int nt = 0; nt < 8; nt++) {
                int rn = 128 + wn * 64 + nt * 8 + grp;
                float2 b = *(const float2*)&st[rn * PITCH + colb];
                uint32_t b0 = __float_as_uint(b.x), b1 = __float_as_uint(b.y);
                mma_tf32(cd[0][nt], a[0], b0, b1);
                mma_tf32(cd[1][nt], a[1], b0, b1);
            }
        }
    }

    // ---- epilogue ----
    #pragma unroll
    for (int mt = 0; mt < 2; mt++) {
        #pragma unroll
        for (int half = 0; half < 2; half++) {
            int row = wm * 32 + mt * 16 + half * 8 + grp;
            int pair = pairs_s[row];
            if (pair >= 0) {
                float w = g_topk_w[pair];
                float* orow = g_outbuf + (size_t)pair * HID + n0;
                #pragma unroll
                for (int nt = 0; nt < 8; nt++) {
                    int col = wn * 64 + nt * 8 + tg * 2;
                    float2 ov;
                    ov.x = cd[mt][nt][half*2 + 0] * w;
                    ov.y = cd[mt][nt][half*2 + 1] * w;
                    *(float2*)(orow + col) = ov;
                }
            }
        }
    }
}

// ---------------- 5. final reduce ----------------
__global__ void reduce_kernel(float* __restrict__ out) {
    int idx = blockIdx.x * blockDim.x + threadIdx.x;
    int t = idx >> 9;
    int h4 = idx & 511;
    const float4* ob = (const float4*)g_outbuf;
    float4 s = ob[(size_t)(t * TOPK) * (HID/4) + h4];
    #pragma unroll
    for (int k = 1; k < TOPK; k++) {
        float4 v = ob[(size_t)(t * TOPK + k) * (HID/4) + h4];
        s.x += v.x; s.y += v.y; s.z += v.z; s.w += v.w;
    }
    ((float4*)out)[idx] = s;
}

// ---------------- launch ----------------
extern "C" void kernel_launch(void* const* d_in, const int* in_sizes, int n_in,
                              void* d_out, int out_size) {
    (void)in_sizes; (void)n_in; (void)out_size;
    const float* hidden = (const float*)d_in[0];
    const float* gate_w = (const float*)d_in[1];
    const float* w_gate = (const float*)d_in[2];
    const float* w_up   = (const float*)d_in[3];
    const float* w_down = (const float*)d_in[4];
    float* out = (float*)d_out;

    cudaFuncSetAttribute(gemm_gateup, cudaFuncAttributeMaxDynamicSharedMemorySize, SMEM_BYTES);
    cudaFuncSetAttribute(gemm_down,   cudaFuncAttributeMaxDynamicSharedMemorySize, SMEM_BYTES);

    router_kernel<<<T_TOK/16, 256>>>(hidden, gate_w);
    bucket_kernel<<<NEXP, 256>>>();
    offsets_kernel<<<1, 32>>>();
    gemm_gateup<<<dim3(T_TOK/128, IDIM/64, NEXP), 256, SMEM_BYTES>>>(hidden, w_gate, w_up);
    gemm_down  <<<dim3(T_TOK/128, HID/128, NEXP), 256, SMEM_BYTES>>>(w_down);
    reduce_kernel<<<(T_TOK*(HID/4))/256, 256>>>(out);
}

// round 4
// speedup vs baseline: 1.0641x; 1.0641x over previous
#include <cuda_runtime.h>
#include <cstdint>

#define T_TOK 2048
#define HID   2048
#define NEXP  64
#define IDIM  768
#define TOPK  8
#define NPAIR (T_TOK*TOPK)   // 16384

#define PITCH 40
#define STG   (256*PITCH)           // floats per stage (A 128 rows + B 128 rows)
#define SMEM_BYTES (2*STG*4)        // 81920 B -> 2 CTAs/SM

// ---------------- device scratch (static, allocation-free) ----------------
__device__ int   g_topk_idx[NPAIR];
__device__ float g_topk_w[NPAIR];
__device__ int   g_counts[NEXP];
__device__ int   g_offsets[NEXP];
__device__ int   g_list[NEXP*T_TOK];
__device__ float g_xbuf[(size_t)T_TOK*HID];            // tf32-rounded hidden
__device__ float g_hbuf[(size_t)(NPAIR+128)*IDIM];     // tf32-rounded silu(g)*u
__device__ float g_outbuf[(size_t)NPAIR*HID];

// ---------------- helpers ----------------
__device__ __forceinline__ float cvt_tf32(float x) {
    uint32_t u; asm("cvt.rna.tf32.f32 %0, %1;" : "=r"(u) : "f"(x));
    return __uint_as_float(u);
}
__device__ __forceinline__ uint32_t cvt_tf32_u(float x) {
    uint32_t u; asm("cvt.rna.tf32.f32 %0, %1;" : "=r"(u) : "f"(x));
    return u;
}

__device__ __forceinline__ void mma_tf32(float* c, const uint32_t* a, uint32_t b0, uint32_t b1) {
    asm volatile(
        "mma.sync.aligned.m16n8k8.row.col.f32.tf32.tf32.f32 "
        "{%0,%1,%2,%3}, {%4,%5,%6,%7}, {%8,%9}, {%0,%1,%2,%3};\n"
        : "+f"(c[0]), "+f"(c[1]), "+f"(c[2]), "+f"(c[3])
        : "r"(a[0]), "r"(a[1]), "r"(a[2]), "r"(a[3]), "r"(b0), "r"(b1));
}

__device__ __forceinline__ void cp_async16(uint32_t smem_addr, const void* gptr, int src_bytes) {
    asm volatile("cp.async.cg.shared.global [%0], [%1], 16, %2;\n"
                 :: "r"(smem_addr), "l"(gptr), "r"(src_bytes));
}
__device__ __forceinline__ void cp_commit() { asm volatile("cp.async.commit_group;\n"); }
template<int N> __device__ __forceinline__ void cp_wait() {
    asm volatile("cp.async.wait_group %0;\n" :: "n"(N));
}

// ---------------- 0. pre-round hidden to tf32 values ----------------
__global__ void convert_x_kernel(const float* __restrict__ x) {
    int idx = blockIdx.x * blockDim.x + threadIdx.x;   // over T*H/4
    float4 v = ((const float4*)x)[idx];
    v.x = cvt_tf32(v.x); v.y = cvt_tf32(v.y);
    v.z = cvt_tf32(v.z); v.w = cvt_tf32(v.w);
    ((float4*)g_xbuf)[idx] = v;
}

// ---------------- 1. router ----------------
__global__ void router_kernel(const float* __restrict__ x, const float* __restrict__ gw) {
    __shared__ float Xs[16][68];
    __shared__ float Gs[64][68];
    __shared__ float Ls[16][64];
    const int tid = threadIdx.x;
    const int t0  = blockIdx.x * 16;
    const int tl  = tid & 15;
    const int eg  = tid >> 4;

    float acc[4] = {0.f, 0.f, 0.f, 0.f};

    for (int kk = 0; kk < HID; kk += 64) {
        {
            int r = tid >> 4, c = (tid & 15) * 4;
            float4 v = *(const float4*)(x + (size_t)(t0 + r) * HID + kk + c);
            Xs[r][c] = v.x; Xs[r][c+1] = v.y; Xs[r][c+2] = v.z; Xs[r][c+3] = v.w;
        }
        #pragma unroll
        for (int i = 0; i < 4; i++) {
            int idx = i * 256 + tid;
            int r = idx >> 4, c = (idx & 15) * 4;
            float4 v = *(const float4*)(gw + (size_t)r * HID + kk + c);
            Gs[r][c] = v.x; Gs[r][c+1] = v.y; Gs[r][c+2] = v.z; Gs[r][c+3] = v.w;
        }
        __syncthreads();
        #pragma unroll 4
        for (int k = 0; k < 64; k += 4) {
            float4 xv = *(const float4*)&Xs[tl][k];
            #pragma unroll
            for (int j = 0; j < 4; j++) {
                float4 gv = *(const float4*)&Gs[eg*4 + j][k];
                acc[j] += xv.x*gv.x + xv.y*gv.y + xv.z*gv.z + xv.w*gv.w;
            }
        }
        __syncthreads();
    }
    #pragma unroll
    for (int j = 0; j < 4; j++) Ls[tl][eg*4 + j] = acc[j];
    __syncthreads();

    const int wid = tid >> 5, lane = tid & 31;
    for (int j = 0; j < 2; j++) {
        const int tok = wid * 2 + j;
        float v0 = Ls[tok][lane];
        float v1 = Ls[tok][lane + 32];
        bool s0 = false, s1 = false;
        float vals[8]; int idxs[8];
        #pragma unroll
        for (int r = 0; r < 8; r++) {
            float bv = -1e30f; int bi = 1 << 20;
            if (!s0) { bv = v0; bi = lane; }
            if (!s1 && (v1 > bv || (v1 == bv && lane + 32 < bi))) { bv = v1; bi = lane + 32; }
            #pragma unroll
            for (int o = 16; o > 0; o >>= 1) {
                float ov = __shfl_xor_sync(0xffffffffu, bv, o);
                int   oi = __shfl_xor_sync(0xffffffffu, bi, o);
                if (ov > bv || (ov == bv && oi < bi)) { bv = ov; bi = oi; }
            }
            vals[r] = bv; idxs[r] = bi;
            if (bi == lane)      s0 = true;
            if (bi == lane + 32) s1 = true;
        }
        if (lane == 0) {
            float m = vals[0];
            float w[8]; float sum = 0.f;
            #pragma unroll
            for (int r = 0; r < 8; r++) { w[r] = __expf(vals[r] - m); sum += w[r]; }
            float inv = 1.f / sum;
            int gt = t0 + tok;
            #pragma unroll
            for (int r = 0; r < 8; r++) {
                g_topk_idx[gt*TOPK + r] = idxs[r];
                g_topk_w  [gt*TOPK + r] = w[r] * inv;
            }
        }
    }
}

// ---------------- 2. bucketing ----------------
__global__ void bucket_kernel() {
    const int e = blockIdx.x;
    const int tid = threadIdx.x;
    __shared__ int warp_tot[8];
    __shared__ int base_s;
    if (tid == 0) base_s = 0;
    __syncthreads();
    const int wid = tid >> 5, lane = tid & 31;
    for (int t0 = 0; t0 < T_TOK; t0 += 256) {
        int t = t0 + tid;
        int slot = -1;
        #pragma unroll
        for (int k = 0; k < TOPK; k++)
            if (g_topk_idx[t*TOPK + k] == e) slot = k;
        unsigned m = __ballot_sync(0xffffffffu, slot >= 0);
        if (lane == 0) warp_tot[wid] = __popc(m);
        __syncthreads();
        int wbase = base_s;
        for (int i = 0; i < wid; i++) wbase += warp_tot[i];
        if (slot >= 0) {
            int pos = wbase + __popc(m & ((1u << lane) - 1u));
            g_list[e*T_TOK + pos] = t*TOPK + slot;
        }
        __syncthreads();
        if (tid == 0) {
            int tot = 0;
            for (int i = 0; i < 8; i++) tot += warp_tot[i];
            base_s += tot;
        }
        __syncthreads();
    }
    if (tid == 0) g_counts[e] = base_s;
}

__global__ void offsets_kernel() {
    if (threadIdx.x == 0 && blockIdx.x == 0) {
        int s = 0;
        for (int e = 0; e < NEXP; e++) { g_offsets[e] = s; s += g_counts[e]; }
    }
}

// ---------------- 3. GEMM1: h = silu(X Wg^T) * (X Wu^T) --------------------
// 128 threads (4 warps, 2m x 2n), block 128 x (64 gate + 64 up), BK=32.
// Warp tile 64m x (32g + 32u). 2-stage overlapped cp.async double buffer.
// A (tokens) pre-rounded in g_xbuf -> no cvt; B cvt'd at fragment load.
__global__ void __launch_bounds__(128, 2)
gemm_gateup(const float* __restrict__ wg,
            const float* __restrict__ wu) {
    const int mb = blockIdx.x, nb = blockIdx.y, e = blockIdx.z;
    const int cnt = g_counts[e];
    if (mb * 128 >= cnt) return;
    const int base = g_offsets[e];

    extern __shared__ float smem[];
    __shared__ int toks_s[128];

    const int tid = threadIdx.x;
    {
        int m = mb * 128 + tid;
        toks_s[tid] = (m < cnt) ? (g_list[e*T_TOK + m] >> 3) : -1;
    }
    __syncthreads();

    const int n0 = nb * 64;
    const float* wg_p = wg + ((size_t)e * IDIM + n0) * HID;
    const float* wu_p = wu + ((size_t)e * IDIM + n0) * HID;

    const uint32_t smem_u = (uint32_t)__cvta_generic_to_shared(smem);

    auto load_stage = [&](int kt, int s) {
        const int kk = kt * 32;
        const uint32_t st = smem_u + (uint32_t)(s * STG) * 4u;
        #pragma unroll
        for (int it = 0; it < 8; it++) {          // A: 1024 float4 / 128 thr
            int fid = it * 128 + tid;
            int r = fid >> 3, c = (fid & 7) * 4;
            int tok = toks_s[r];
            const float* src = (tok >= 0) ? g_xbuf + (size_t)tok * HID + kk + c : g_xbuf;
            cp_async16(st + (uint32_t)(r * PITCH + c) * 4u, src, (tok >= 0) ? 16 : 0);
        }
        #pragma unroll
        for (int it = 0; it < 8; it++) {          // B: 64 gate + 64 up rows
            int fid = it * 128 + tid;
            int r = fid >> 3, c = (fid & 7) * 4;
            const float* src = (r < 64) ? wg_p + (size_t)r * HID + kk + c
                                        : wu_p + (size_t)(r - 64) * HID + kk + c;
            cp_async16(st + (uint32_t)((128 + r) * PITCH + c) * 4u, src, 16);
        }
    };

    float cg[4][4][4], cu[4][4][4];
    #pragma unroll
    for (int a = 0; a < 4; a++)
        #pragma unroll
        for (int b = 0; b < 4; b++)
            #pragma unroll
            for (int c = 0; c < 4; c++) { cg[a][b][c] = 0.f; cu[a][b][c] = 0.f; }

    const int wid = tid >> 5, lane = tid & 31;
    const int wm = wid & 1, wn = wid >> 1;        // 2 x 2 warp grid
    const int grp = lane >> 2, tg = lane & 3;

    const int KT = HID / 32;                       // 64
    load_stage(0, 0); cp_commit();

    for (int kt = 0; kt < KT; kt++) {
        cp_wait<0>();
        __syncthreads();                           // stage kt ready; compute(kt-1) done
        if (kt + 1 < KT) { load_stage(kt + 1, (kt + 1) & 1); cp_commit(); }

        const float* st = smem + (kt & 1) * STG;
        #pragma unroll
        for (int s = 0; s < 4; s++) {
            const int colb = s * 8 + tg * 2;
            uint32_t a[4][4];
            #pragma unroll
            for (int mt = 0; mt < 4; mt++) {
                int r0 = wm * 64 + mt * 16 + grp;
                float2 x = *(const float2*)&st[ r0      * PITCH + colb];
                float2 y = *(const float2*)&st[(r0 + 8) * PITCH + colb];
                a[mt][0] = __float_as_uint(x.x); a[mt][1] = __float_as_uint(y.x);
                a[mt][2] = __float_as_uint(x.y); a[mt][3] = __float_as_uint(y.y);
            }
            #pragma unroll
            for (int nt = 0; nt < 4; nt++) {
                int rn = 128 + wn * 32 + nt * 8 + grp;
                float2 g = *(const float2*)&st[ rn       * PITCH + colb];
                float2 u = *(const float2*)&st[(rn + 64) * PITCH + colb];
                uint32_t g0 = cvt_tf32_u(g.x), g1 = cvt_tf32_u(g.y);
                uint32_t u0 = cvt_tf32_u(u.x), u1 = cvt_tf32_u(u.y);
                #pragma unroll
                for (int mt = 0; mt < 4; mt++) {
                    mma_tf32(cg[mt][nt], a[mt], g0, g1);
                    mma_tf32(cu[mt][nt], a[mt], u0, u1);
                }
            }
        }
        __syncthreads();                           // protect stage before overwrite next iter
    }

    // ---- epilogue: silu(g)*u, tf32-rounded -> g_hbuf ----
    #pragma unroll
    for (int mt = 0; mt < 4; mt++) {
        #pragma unroll
        for (int half = 0; half < 2; half++) {
            int row = wm * 64 + mt * 16 + half * 8 + grp;
            int m = mb * 128 + row;
            if (m < cnt) {
                float* hrow = g_hbuf + (size_t)(base + m) * IDIM + n0;
                #pragma unroll
                for (int nt = 0; nt < 4; nt++) {
                    int col = wn * 32 + nt * 8 + tg * 2;
                    float g0 = cg[mt][nt][half*2 + 0], u0 = cu[mt][nt][half*2 + 0];
                    float g1 = cg[mt][nt][half*2 + 1], u1 = cu[mt][nt][half*2 + 1];
                    float2 hv;
                    hv.x = cvt_tf32(g0 * u0 / (1.f + __expf(-g0)));
                    hv.y = cvt_tf32(g1 * u1 / (1.f + __expf(-g1)));
                    *(float2*)(hrow + col) = hv;
                }
            }
        }
    }
}

// ---------------- 4. GEMM2: y = (h Wd^T) * combine_w -> g_outbuf ----------
// 128 threads (4 warps, 2m x 2n), block 128x128, warp tile 64x64.
__global__ void __launch_bounds__(128, 2)
gemm_down(const float* __restrict__ wd) {
    const int mb = blockIdx.x, nb = blockIdx.y, e = blockIdx.z;
    const int cnt = g_counts[e];
    if (mb * 128 >= cnt) return;
    const int base = g_offsets[e];

    extern __shared__ float smem[];
    __shared__ int pairs_s[128];

    const int tid = threadIdx.x;
    {
        int m = mb * 128 + tid;
        pairs_s[tid] = (m < cnt) ? g_list[e*T_TOK + m] : -1;
    }
    __syncthreads();

    const int n0 = nb * 128;
    const float* wd_p  = wd + ((size_t)e * HID + n0) * IDIM;
    const float* arow0 = g_hbuf + (size_t)(base + mb * 128) * IDIM;

    const uint32_t smem_u = (uint32_t)__cvta_generic_to_shared(smem);

    auto load_stage = [&](int kt, int s) {
        const int kk = kt * 32;
        const uint32_t st = smem_u + (uint32_t)(s * STG) * 4u;
        #pragma unroll
        for (int it = 0; it < 8; it++) {
            int fid = it * 128 + tid;
            int r = fid >> 3, c = (fid & 7) * 4;
            bool val = pairs_s[r] >= 0;
            const float* src = val ? arow0 + (size_t)r * IDIM + kk + c : g_hbuf;
            cp_async16(st + (uint32_t)(r * PITCH + c) * 4u, src, val ? 16 : 0);
        }
        #pragma unroll
        for (int it = 0; it < 8; it++) {
            int fid = it * 128 + tid;
            int r = fid >> 3, c = (fid & 7) * 4;
            cp_async16(st + (uint32_t)((128 + r) * PITCH + c) * 4u,
                       wd_p + (size_t)r * IDIM + kk + c, 16);
        }
    };

    float cd[4][8][4];
    #pragma unroll
    for (int a = 0; a < 4; a++)
        #pragma unroll
        for (int b = 0; b < 8; b++)
            #pragma unroll
            for (int c = 0; c < 4; c++) cd[a][b][c] = 0.f;

    const int wid = tid >> 5, lane = tid & 31;
    const int wm = wid & 1, wn = wid >> 1;
    const int grp = lane >> 2, tg = lane & 3;

    const int KT = IDIM / 32;                      // 24
    load_stage(0, 0); cp_commit();

    for (int kt = 0; kt < KT; kt++) {
        cp_wait<0>();
        __syncthreads();
        if (kt + 1 < KT) { load_stage(kt + 1, (kt + 1) & 1); cp_commit(); }

        const float* st = smem + (kt & 1) * STG;
        #pragma unroll
        for (int s = 0; s < 4; s++) {
            const int colb = s * 8 + tg * 2;
            uint32_t a[4][4];
            #pragma unroll
            for (int mt = 0; mt < 4; mt++) {
                int r0 = wm * 64 + mt * 16 + grp;
                float2 x = *(const float2*)&st[ r0      * PITCH + colb];
                float2 y = *(const float2*)&st[(r0 + 8) * PITCH + colb];
                a[mt][0] = __float_as_uint(x.x); a[mt][1] = __float_as_uint(y.x);
                a[mt][2] = __float_as_uint(x.y); a[mt][3] = __float_as_uint(y.y);
            }
            #pragma unroll
            for (int nt = 0; nt < 8; nt++) {
                int rn = 128 + wn * 64 + nt * 8 + grp;
                float2 b = *(const float2*)&st[rn * PITCH + colb];
                uint32_t b0 = cvt_tf32_u(b.x), b1 = cvt_tf32_u(b.y);
                #pragma unroll
                for (int mt = 0; mt < 4; mt++)
                    mma_tf32(cd[mt][nt], a[mt], b0, b1);
            }
        }
        __syncthreads();
    }

    // ---- epilogue: scale by combine weight, write per-pair row ----
    #pragma unroll
    for (int mt = 0; mt < 4; mt++) {
        #pragma unroll
        for (int half = 0; half < 2; half++) {
            int row = wm * 64 + mt * 16 + half * 8 + grp;
            int pair = pairs_s[row];
            if (pair >= 0) {
                float w = g_topk_w[pair];
                float* orow = g_outbuf + (size_t)pair * HID + n0;
                #pragma unroll
                for (int nt = 0; nt < 8; nt++) {
                    int col = wn * 64 + nt * 8 + tg * 2;
                    float2 ov;
                    ov.x = cd[mt][nt][half*2 + 0] * w;
                    ov.y = cd[mt][nt][half*2 + 1] * w;
                    *(float2*)(orow + col) = ov;
                }
            }
        }
    }
}

// ---------------- 5. final reduce ----------------
__global__ void reduce_kernel(float* __restrict__ out) {
    int idx = blockIdx.x * blockDim.x + threadIdx.x;
    int t = idx >> 9;
    int h4 = idx & 511;
    const float4* ob = (const float4*)g_outbuf;
    float4 s = ob[(size_t)(t * TOPK) * (HID/4) + h4];
    #pragma unroll
    for (int k = 1; k < TOPK; k++) {
        float4 v = ob[(size_t)(t * TOPK + k) * (HID/4) + h4];
        s.x += v.x; s.y += v.y; s.z += v.z; s.w += v.w;
    }
    ((float4*)out)[idx] = s;
}

// ---------------- launch ----------------
extern "C" void kernel_launch(void* const* d_in, const int* in_sizes, int n_in,
                              void* d_out, int out_size) {
    (void)in_sizes; (void)n_in; (void)out_size;
    const float* hidden = (const float*)d_in[0];
    const float* gate_w = (const float*)d_in[1];
    const float* w_gate = (const float*)d_in[2];
    const float* w_up   = (const float*)d_in[3];
    const float* w_down = (const float*)d_in[4];
    float* out = (float*)d_out;

    cudaFuncSetAttribute(gemm_gateup, cudaFuncAttributeMaxDynamicSharedMemorySize, SMEM_BYTES);
    cudaFuncSetAttribute(gemm_down,   cudaFuncAttributeMaxDynamicSharedMemorySize, SMEM_BYTES);

    convert_x_kernel<<<(T_TOK*HID/4)/256, 256>>>(hidden);
    router_kernel<<<T_TOK/16, 256>>>(hidden, gate_w);
    bucket_kernel<<<NEXP, 256>>>();
    offsets_kernel<<<1, 32>>>();
    gemm_gateup<<<dim3(T_TOK/128, IDIM/64, NEXP), 128, SMEM_BYTES>>>(w_gate, w_up);
    gemm_down  <<<dim3(T_TOK/128, HID/128, NEXP), 128, SMEM_BYTES>>>(w_down);
    reduce_kernel<<<(T_TOK*(HID/4))/256, 256>>>(out);
}

// round 7
// speedup vs baseline: 1.2226x; 1.1490x over previous
#include <cuda_runtime.h>
#include <cstdint>

#define T_TOK 2048
#define HID   2048
#define NEXP  64
#define IDIM  768
#define TOPK  8
#define NPAIR (T_TOK*TOPK)   // 16384

#define STG_BYTES 32768             // A 128 rows x 128B + B 128 rows x 128B, swizzled
#define NSTAGE 3
#define DYN_SMEM (NSTAGE*STG_BYTES + 1024)

// ---------------- device scratch (static, allocation-free) ----------------
__device__ int   g_topk_idx[NPAIR];
__device__ float g_topk_w[NPAIR];
__device__ int   g_counts[NEXP];
__device__ int   g_offsets[NEXP];
__device__ int   g_list[NEXP*T_TOK];
__device__ float g_xbuf[(size_t)T_TOK*HID];            // tf32-rounded hidden
__device__ float g_hbuf[(size_t)(NPAIR+128)*IDIM];     // tf32-rounded silu(g)*u
__device__ float g_outbuf[(size_t)NPAIR*HID];

// ---------------- helpers ----------------
__device__ __forceinline__ float cvt_tf32(float x) {
    uint32_t u; asm("cvt.rna.tf32.f32 %0, %1;" : "=r"(u) : "f"(x));
    return __uint_as_float(u);
}
__device__ __forceinline__ void mma_tf32(float* c, const uint32_t* a, uint32_t b0, uint32_t b1) {
    asm volatile(
        "mma.sync.aligned.m16n8k8.row.col.f32.tf32.tf32.f32 "
        "{%0,%1,%2,%3}, {%4,%5,%6,%7}, {%8,%9}, {%0,%1,%2,%3};\n"
        : "+f"(c[0]), "+f"(c[1]), "+f"(c[2]), "+f"(c[3])
        : "r"(a[0]), "r"(a[1]), "r"(a[2]), "r"(a[3]), "r"(b0), "r"(b1));
}
__device__ __forceinline__ void cp_async16(uint32_t smem_addr, const void* gptr, int src_bytes) {
    asm volatile("cp.async.cg.shared.global [%0], [%1], 16, %2;\n"
                 :: "r"(smem_addr), "l"(gptr), "r"(src_bytes));
}
__device__ __forceinline__ void cp_commit() { asm volatile("cp.async.commit_group;\n"); }
template<int N> __device__ __forceinline__ void cp_wait() {
    asm volatile("cp.async.wait_group %0;\n" :: "n"(N));
}

// ---------------- 0. pre-round hidden to tf32 values ----------------
__global__ void convert_x_kernel(const float* __restrict__ x) {
    int idx = blockIdx.x * blockDim.x + threadIdx.x;
    float4 v = ((const float4*)x)[idx];
    v.x = cvt_tf32(v.x); v.y = cvt_tf32(v.y);
    v.z = cvt_tf32(v.z); v.w = cvt_tf32(v.w);
    ((float4*)g_xbuf)[idx] = v;
}

// ---------------- 1. router ----------------
__global__ void router_kernel(const float* __restrict__ x, const float* __restrict__ gw) {
    __shared__ float Xs[16][68];
    __shared__ float Gs[64][68];
    __shared__ float Ls[16][64];
    const int tid = threadIdx.x;
    const int t0  = blockIdx.x * 16;
    const int tl  = tid & 15;
    const int eg  = tid >> 4;

    float acc[4] = {0.f, 0.f, 0.f, 0.f};

    for (int kk = 0; kk < HID; kk += 64) {
        {
            int r = tid >> 4, c = (tid & 15) * 4;
            float4 v = *(const float4*)(x + (size_t)(t0 + r) * HID + kk + c);
            Xs[r][c] = v.x; Xs[r][c+1] = v.y; Xs[r][c+2] = v.z; Xs[r][c+3] = v.w;
        }
        #pragma unroll
        for (int i = 0; i < 4; i++) {
            int idx = i * 256 + tid;
            int r = idx >> 4, c = (idx & 15) * 4;
            float4 v = *(const float4*)(gw + (size_t)r * HID + kk + c);
            Gs[r][c] = v.x; Gs[r][c+1] = v.y; Gs[r][c+2] = v.z; Gs[r][c+3] = v.w;
        }
        __syncthreads();
        #pragma unroll 4
        for (int k = 0; k < 64; k += 4) {
            float4 xv = *(const float4*)&Xs[tl][k];
            #pragma unroll
            for (int j = 0; j < 4; j++) {
                float4 gv = *(const float4*)&Gs[eg*4 + j][k];
                acc[j] += xv.x*gv.x + xv.y*gv.y + xv.z*gv.z + xv.w*gv.w;
            }
        }
        __syncthreads();
    }
    #pragma unroll
    for (int j = 0; j < 4; j++) Ls[tl][eg*4 + j] = acc[j];
    __syncthreads();

    const int wid = tid >> 5, lane = tid & 31;
    for (int j = 0; j < 2; j++) {
        const int tok = wid * 2 + j;
        float v0 = Ls[tok][lane];
        float v1 = Ls[tok][lane + 32];
        bool s0 = false, s1 = false;
        float vals[8]; int idxs[8];
        #pragma unroll
        for (int r = 0; r < 8; r++) {
            float bv = -1e30f; int bi = 1 << 20;
            if (!s0) { bv = v0; bi = lane; }
            if (!s1 && (v1 > bv || (v1 == bv && lane + 32 < bi))) { bv = v1; bi = lane + 32; }
            #pragma unroll
            for (int o = 16; o > 0; o >>= 1) {
                float ov = __shfl_xor_sync(0xffffffffu, bv, o);
                int   oi = __shfl_xor_sync(0xffffffffu, bi, o);
                if (ov > bv || (ov == bv && oi < bi)) { bv = ov; bi = oi; }
            }
            vals[r] = bv; idxs[r] = bi;
            if (bi == lane)      s0 = true;
            if (bi == lane + 32) s1 = true;
        }
        if (lane == 0) {
            float m = vals[0];
            float w[8]; float sum = 0.f;
            #pragma unroll
            for (int r = 0; r < 8; r++) { w[r] = __expf(vals[r] - m); sum += w[r]; }
            float inv = 1.f / sum;
            int gt = t0 + tok;
            #pragma unroll
            for (int r = 0; r < 8; r++) {
                g_topk_idx[gt*TOPK + r] = idxs[r];
                g_topk_w  [gt*TOPK + r] = w[r] * inv;
            }
        }
    }
}

// ---------------- 2. bucketing ----------------
__global__ void bucket_kernel() {
    const int e = blockIdx.x;
    const int tid = threadIdx.x;
    __shared__ int warp_tot[8];
    __shared__ int base_s;
    if (tid == 0) base_s = 0;
    __syncthreads();
    const int wid = tid >> 5, lane = tid & 31;
    for (int t0 = 0; t0 < T_TOK; t0 += 256) {
        int t = t0 + tid;
        int slot = -1;
        #pragma unroll
        for (int k = 0; k < TOPK; k++)
            if (g_topk_idx[t*TOPK + k] == e) slot = k;
        unsigned m = __ballot_sync(0xffffffffu, slot >= 0);
        if (lane == 0) warp_tot[wid] = __popc(m);
        __syncthreads();
        int wbase = base_s;
        for (int i = 0; i < wid; i++) wbase += warp_tot[i];
        if (slot >= 0) {
            int pos = wbase + __popc(m & ((1u << lane) - 1u));
            g_list[e*T_TOK + pos] = t*TOPK + slot;
        }
        __syncthreads();
        if (tid == 0) {
            int tot = 0;
            for (int i = 0; i < 8; i++) tot += warp_tot[i];
            base_s += tot;
        }
        __syncthreads();
    }
    if (tid == 0) g_counts[e] = base_s;
}

__global__ void offsets_kernel() {
    if (threadIdx.x == 0 && blockIdx.x == 0) {
        int s = 0;
        for (int e = 0; e < NEXP; e++) { g_offsets[e] = s; s += g_counts[e]; }
    }
}

// =====================================================================
// Swizzled stage layout: rows 0..127 = A, rows 128..255 = B, 128 B/row.
// Chunk (16B) c of local row r stored at byte r*128 + ((c ^ (r&7))*16).
// k-permutation: MMA step s = 2p+j, k-slot h in {0,1} (k = tg / tg+4):
//   value lives in chunk (2*tg + p), float index (2j + h) within the chunk.
// Fragment LDS.128 of chunk (2tg+p)^grp is conflict-free per 8-lane phase.
// =====================================================================

// ---------------- 3. GEMM1: h = silu(X Wg^T) * (X Wu^T) ----------------
// 256 thr (8 warps, 2m x 4n), block 128m x 64 IDIM cols (gate+up), BK=32.
// Warp tile 64m x 16 IDIM cols (x2 matrices).
__global__ void __launch_bounds__(256, 2)
gemm_gateup(const float* __restrict__ wg,
            const float* __restrict__ wu) {
    const int mb = blockIdx.x, nb = blockIdx.y, e = blockIdx.z;
    const int cnt = g_counts[e];
    if (mb * 128 >= cnt) return;
    const int base = g_offsets[e];

    extern __shared__ char smraw[];
    uint32_t sm0 = (uint32_t)__cvta_generic_to_shared(smraw);
    uint32_t smA = (sm0 + 1023u) & ~1023u;
    char*    smg = smraw + (smA - sm0);

    __shared__ int toks_s[128];

    const int tid = threadIdx.x;
    if (tid < 128) {
        int m = mb * 128 + tid;
        toks_s[tid] = (m < cnt) ? (g_list[e*T_TOK + m] >> 3) : -1;
    }
    __syncthreads();

    const int n0 = nb * 64;
    const float* wg_p = wg + ((size_t)e * IDIM + n0) * HID;
    const float* wu_p = wu + ((size_t)e * IDIM + n0) * HID;

    auto load_stage = [&](int kt, int s) {
        const int kk = kt * 32;
        const uint32_t st = smA + (uint32_t)(s * STG_BYTES);
        #pragma unroll
        for (int it = 0; it < 4; it++) {          // A: 1024 chunks
            int fid = it * 256 + tid;
            int r = fid >> 3, c = fid & 7;
            int tok = toks_s[r];
            const float* src = (tok >= 0) ? g_xbuf + (size_t)tok * HID + kk + c * 4 : g_xbuf;
            cp_async16(st + (uint32_t)(r * 128 + ((c ^ (r & 7)) * 16)), src, (tok >= 0) ? 16 : 0);
        }
        #pragma unroll
        for (int it = 0; it < 4; it++) {          // B: 64 gate + 64 up rows
            int fid = it * 256 + tid;
            int r = fid >> 3, c = fid & 7;
            const float* src = (r < 64) ? wg_p + (size_t)r * HID + kk + c * 4
                                        : wu_p + (size_t)(r - 64) * HID + kk + c * 4;
            cp_async16(st + (uint32_t)(16384 + r * 128 + ((c ^ (r & 7)) * 16)), src, 16);
        }
    };

    float cg[4][2][4], cu[4][2][4];
    #pragma unroll
    for (int a = 0; a < 4; a++)
        #pragma unroll
        for (int b = 0; b < 2; b++)
            #pragma unroll
            for (int c = 0; c < 4; c++) { cg[a][b][c] = 0.f; cu[a][b][c] = 0.f; }

    const int wid = tid >> 5, lane = tid & 31;
    const int wm = wid & 1, wn = wid >> 1;        // 2m x 4n
    const int grp = lane >> 2, tg = lane & 3;

    const int KT = HID / 32;                       // 64
    load_stage(0, 0); cp_commit();
    load_stage(1, 1); cp_commit();

    for (int kt = 0; kt < KT; kt++) {
        cp_wait<1>();
        __syncthreads();
        if (kt + 2 < KT) load_stage(kt + 2, (kt + 2) % 3);
        cp_commit();

        const char* st = smg + (kt % 3) * STG_BYTES;
        #pragma unroll
        for (int p = 0; p < 2; p++) {
            const int cA = ((2 * tg + p) ^ grp) * 16;   // chunk byte offset in row
            float4 bg[2], bu[2];
            #pragma unroll
            for (int nf = 0; nf < 2; nf++) {
                int br = 128 + wn * 16 + nf * 8 + grp;
                float4 v = *(const float4*)(st + br * 128 + cA);
                v.x = cvt_tf32(v.x); v.y = cvt_tf32(v.y);
                v.z = cvt_tf32(v.z); v.w = cvt_tf32(v.w);
                bg[nf] = v;
                float4 w = *(const float4*)(st + (br + 64) * 128 + cA);
                w.x = cvt_tf32(w.x); w.y = cvt_tf32(w.y);
                w.z = cvt_tf32(w.z); w.w = cvt_tf32(w.w);
                bu[nf] = w;
            }
            #pragma unroll
            for (int mt = 0; mt < 4; mt++) {
                int ar = wm * 64 + mt * 16 + grp;
                float4 alo = *(const float4*)(st + ar * 128 + cA);
                float4 ahi = *(const float4*)(st + (ar + 8) * 128 + cA);
                const float* aloF = (const float*)&alo;
                const float* ahiF = (const float*)&ahi;
                #pragma unroll
                for (int j = 0; j < 2; j++) {
                    uint32_t a[4];
                    a[0] = __float_as_uint(aloF[2*j]);
                    a[1] = __float_as_uint(ahiF[2*j]);
                    a[2] = __float_as_uint(aloF[2*j + 1]);
                    a[3] = __float_as_uint(ahiF[2*j + 1]);
                    #pragma unroll
                    for (int nf = 0; nf < 2; nf++) {
                        const float* bgF = (const float*)&bg[nf];
                        const float* buF = (const float*)&bu[nf];
                        mma_tf32(cg[mt][nf], a, __float_as_uint(bgF[2*j]), __float_as_uint(bgF[2*j+1]));
                        mma_tf32(cu[mt][nf], a, __float_as_uint(buF[2*j]), __float_as_uint(buF[2*j+1]));
                    }
                }
            }
        }
    }

    // ---- epilogue: silu(g)*u, tf32-rounded -> g_hbuf ----
    #pragma unroll
    for (int mt = 0; mt < 4; mt++) {
        #pragma unroll
        for (int hl = 0; hl < 2; hl++) {
            int row = wm * 64 + mt * 16 + hl * 8 + grp;
            int m = mb * 128 + row;
            if (m < cnt) {
                float* hrow = g_hbuf + (size_t)(base + m) * IDIM + n0;
                #pragma unroll
                for (int nf = 0; nf < 2; nf++) {
                    int col = wn * 16 + nf * 8 + tg * 2;
                    float g0 = cg[mt][nf][hl*2 + 0], u0 = cu[mt][nf][hl*2 + 0];
                    float g1 = cg[mt][nf][hl*2 + 1], u1 = cu[mt][nf][hl*2 + 1];
                    float2 hv;
                    hv.x = cvt_tf32(g0 * u0 / (1.f + __expf(-g0)));
                    hv.y = cvt_tf32(g1 * u1 / (1.f + __expf(-g1)));
                    *(float2*)(hrow + col) = hv;
                }
            }
        }
    }
}

// ---------------- 4. GEMM2: y = (h Wd^T) * combine_w -> g_outbuf ----------
// 256 thr (8 warps, 2m x 4n), block 128m x 128n(HID), warp tile 64 x 32.
__global__ void __launch_bounds__(256, 2)
gemm_down(const float* __restrict__ wd) {
    const int mb = blockIdx.x, nb = blockIdx.y, e = blockIdx.z;
    const int cnt = g_counts[e];
    if (mb * 128 >= cnt) return;
    const int base = g_offsets[e];

    extern __shared__ char smraw[];
    uint32_t sm0 = (uint32_t)__cvta_generic_to_shared(smraw);
    uint32_t smA = (sm0 + 1023u) & ~1023u;
    char*    smg = smraw + (smA - sm0);

    __shared__ int pairs_s[128];

    const int tid = threadIdx.x;
    if (tid < 128) {
        int m = mb * 128 + tid;
        pairs_s[tid] = (m < cnt) ? g_list[e*T_TOK + m] : -1;
    }
    __syncthreads();

    const int n0 = nb * 128;
    const float* wd_p  = wd + ((size_t)e * HID + n0) * IDIM;
    const float* arow0 = g_hbuf + (size_t)(base + mb * 128) * IDIM;

    auto load_stage = [&](int kt, int s) {
        const int kk = kt * 32;
        const uint32_t st = smA + (uint32_t)(s * STG_BYTES);
        #pragma unroll
        for (int it = 0; it < 4; it++) {
            int fid = it * 256 + tid;
            int r = fid >> 3, c = fid & 7;
            bool val = pairs_s[r] >= 0;
            const float* src = val ? arow0 + (size_t)r * IDIM + kk + c * 4 : g_hbuf;
            cp_async16(st + (uint32_t)(r * 128 + ((c ^ (r & 7)) * 16)), src, val ? 16 : 0);
        }
        #pragma unroll
        for (int it = 0; it < 4; it++) {
            int fid = it * 256 + tid;
            int r = fid >> 3, c = fid & 7;
            cp_async16(st + (uint32_t)(16384 + r * 128 + ((c ^ (r & 7)) * 16)),
                       wd_p + (size_t)r * IDIM + kk + c * 4, 16);
        }
    };

    float cd[4][4][4];
    #pragma unroll
    for (int a = 0; a < 4; a++)
        #pragma unroll
        for (int b = 0; b < 4; b++)
            #pragma unroll
            for (int c = 0; c < 4; c++) cd[a][b][c] = 0.f;

    const int wid = tid >> 5, lane = tid & 31;
    const int wm = wid & 1, wn = wid >> 1;
    const int grp = lane >> 2, tg = lane & 3;

    const int KT = IDIM / 32;                      // 24
    load_stage(0, 0); cp_commit();
    load_stage(1, 1); cp_commit();

    for (int kt = 0; kt < KT; kt++) {
        cp_wait<1>();
        __syncthreads();
        if (kt + 2 < KT) load_stage(kt + 2, (kt + 2) % 3);
        cp_commit();

        const char* st = smg + (kt % 3) * STG_BYTES;
        #pragma unroll
        for (int p = 0; p < 2; p++) {
            const int cA = ((2 * tg + p) ^ grp) * 16;
            float4 bw[4];
            #pragma unroll
            for (int nf = 0; nf < 4; nf++) {
                int br = 128 + wn * 32 + nf * 8 + grp;
                float4 v = *(const float4*)(st + br * 128 + cA);
                v.x = cvt_tf32(v.x); v.y = cvt_tf32(v.y);
                v.z = cvt_tf32(v.z); v.w = cvt_tf32(v.w);
                bw[nf] = v;
            }
            #pragma unroll
            for (int mt = 0; mt < 4; mt++) {
                int ar = wm * 64 + mt * 16 + grp;
                float4 alo = *(const float4*)(st + ar * 128 + cA);
                float4 ahi = *(const float4*)(st + (ar + 8) * 128 + cA);
                const float* aloF = (const float*)&alo;
                const float* ahiF = (const float*)&ahi;
                #pragma unroll
                for (int j = 0; j < 2; j++) {
                    uint32_t a[4];
                    a[0] = __float_as_uint(aloF[2*j]);
                    a[1] = __float_as_uint(ahiF[2*j]);
                    a[2] = __float_as_uint(aloF[2*j + 1]);
                    a[3] = __float_as_uint(ahiF[2*j + 1]);
                    #pragma unroll
                    for (int nf = 0; nf < 4; nf++) {
                        const float* bF = (const float*)&bw[nf];
                        mma_tf32(cd[mt][nf], a, __float_as_uint(bF[2*j]), __float_as_uint(bF[2*j+1]));
                    }
                }
            }
        }
    }

    // ---- epilogue: scale by combine weight, write per-pair row ----
    #pragma unroll
    for (int mt = 0; mt < 4; mt++) {
        #pragma unroll
        for (int hl = 0; hl < 2; hl++) {
            int row = wm * 64 + mt * 16 + hl * 8 + grp;
            int pair = pairs_s[row];
            if (pair >= 0) {
                float w = g_topk_w[pair];
                float* orow = g_outbuf + (size_t)pair * HID + n0;
                #pragma unroll
                for (int nf = 0; nf < 4; nf++) {
                    int col = wn * 32 + nf * 8 + tg * 2;
                    float2 ov;
                    ov.x = cd[mt][nf][hl*2 + 0] * w;
                    ov.y = cd[mt][nf][hl*2 + 1] * w;
                    *(float2*)(orow + col) = ov;
                }
            }
        }
    }
}

// ---------------- 5. final reduce ----------------
__global__ void reduce_kernel(float* __restrict__ out) {
    int idx = blockIdx.x * blockDim.x + threadIdx.x;
    int t = idx >> 9;
    int h4 = idx & 511;
    const float4* ob = (const float4*)g_outbuf;
    float4 s = ob[(size_t)(t * TOPK) * (HID/4) + h4];
    #pragma unroll
    for (int k = 1; k < TOPK; k++) {
        float4 v = ob[(size_t)(t * TOPK + k) * (HID/4) + h4];
        s.x += v.x; s.y += v.y; s.z += v.z; s.w += v.w;
    }
    ((float4*)out)[idx] = s;
}

// ---------------- launch ----------------
extern "C" void kernel_launch(void* const* d_in, const int* in_sizes, int n_in,
                              void* d_out, int out_size) {
    (void)in_sizes; (void)n_in; (void)out_size;
    const float* hidden = (const float*)d_in[0];
    const float* gate_w = (const float*)d_in[1];
    const float* w_gate = (const float*)d_in[2];
    const float* w_up   = (const float*)d_in[3];
    const float* w_down = (const float*)d_in[4];
    float* out = (float*)d_out;

    cudaFuncSetAttribute(gemm_gateup, cudaFuncAttributeMaxDynamicSharedMemorySize, DYN_SMEM);
    cudaFuncSetAttribute(gemm_down,   cudaFuncAttributeMaxDynamicSharedMemorySize, DYN_SMEM);

    convert_x_kernel<<<(T_TOK*HID/4)/256, 256>>>(hidden);
    router_kernel<<<T_TOK/16, 256>>>(hidden, gate_w);
    bucket_kernel<<<NEXP, 256>>>();
    offsets_kernel<<<1, 32>>>();
    gemm_gateup<<<dim3(T_TOK/128, IDIM/64, NEXP), 256, DYN_SMEM>>>(w_gate, w_up);
    gemm_down  <<<dim3(T_TOK/128, HID/128, NEXP), 256, DYN_SMEM>>>(w_down);
    reduce_kernel<<<(T_TOK*(HID/4))/256, 256>>>(out);
}